// round 9
// baseline (speedup 1.0000x reference)
#include <cuda_runtime.h>
#include <cstdint>
#include <cstddef>

// Problem shape (fixed by setup_inputs)
#define B_    8
#define S_    4096
#define D_    1024

#define SEGR  64                   // rows per warp-segment
#define NSEG  (S_ / SEGR)          // 64 segments per chain
#define NDSL  (D_ / 128)           // 8 d-slices of 128 cols
#define NCHN  (B_ * NDSL)          // 64 chains
#define WPB   4                    // warps per block
#define NBLK  ((NCHN * NSEG) / WPB)  // 1024 blocks
#define TPREP 256
#define SPAN  (S_ / TPREP)         // 16

// Static device scratch
__device__ float4        g_tbl[B_][S_];         // (m, n, w, 0) per timestep
__device__ int           g_fr[B_][NSEG];        // first reset row in segment (abs), else seg end
__device__ volatile int  g_sf[NCHN][NSEG];      // segment final-S published
__device__ float4        g_sv[NCHN][NSEG][32];  // segment final S per lane

// ---------------------------------------------------------------------------
// Prep: one block per batch. dtype detect, exact pos over S (span scan),
// write affine table, per-segment first-reset, clear handoff flags.
// ---------------------------------------------------------------------------
__global__ void __launch_bounds__(TPREP)
prep_kernel(const int* __restrict__ idw)        // raw 32-bit word view of ids
{
    __shared__ unsigned short pos[S_];
    __shared__ unsigned short spanEnd[TPREP];
    __shared__ unsigned short spanCarry[TPREP];
    __shared__ unsigned char  spanFR[TPREP];
    __shared__ int modeAcc;
    __shared__ int s_fr[NSEG];

    const int b   = blockIdx.x;
    const int tid = threadIdx.x;
    const int l   = tid & 31;

    if (tid == 0) modeAcc = 0;
    if (tid < NSEG) s_fr[tid] = S_;
    for (int i = tid; i < NDSL * NSEG; i += TPREP)      // clear this batch's flags
        g_sf[b * NDSL + (i / NSEG)][i % NSEG] = 0;
    __syncthreads();

    // dtype detect: words [0,4096) in-bounds under both interpretations; odd
    // words are int64 hi-halves (all zero) iff int64.
    {
        int acc = 0;
        #pragma unroll
        for (int k = 0; k < 8; k++)
            acc |= __ldg(&idw[2 * (tid * 8 + k) + 1]);
        #pragma unroll
        for (int o = 16; o; o >>= 1) acc |= __shfl_xor_sync(~0u, acc, o);
        if (l == 0) atomicOr(&modeAcc, acc);
    }
    __syncthreads();
    const bool mode64 = (modeAcc == 0);

    // pass A: each thread scans SPAN consecutive timesteps
    {
        const int base = tid * SPAN;
        int p = 0, fr = SPAN;
        #pragma unroll
        for (int j = 0; j < SPAN; j++) {
            int f;
            if (mode64) {
                int2 v = __ldg(((const int2*)idw) + (size_t)b * S_ + base + j);
                f = (v.x == 1) & (v.y == 0);
            } else {
                f = (__ldg(idw + (size_t)b * S_ + base + j) == 1);
            }
            p = f ? 1 : p + 1;
            if (f && fr == SPAN) fr = j;
            pos[base + j] = (unsigned short)p;
        }
        spanEnd[tid] = (unsigned short)p;
        spanFR[tid]  = (unsigned char)fr;
    }
    __syncthreads();

    // span scan (warp 0): carry = run length entering each span
    if (tid < 32) {
        int a = 0, bb = 1;
        #pragma unroll
        for (int k = 0; k < 8; k++) {
            int s  = tid * 8 + k;
            int hr = (spanFR[s] < SPAN);
            int e  = spanEnd[s];
            if (hr) { a = e; bb = 0; } else { a += SPAN; }
        }
        #pragma unroll
        for (int o = 1; o < 32; o <<= 1) {
            int pa = __shfl_up_sync(~0u, a,  o);
            int pb = __shfl_up_sync(~0u, bb, o);
            if (tid >= o) { a = a + bb * pa; bb = bb * pb; }
        }
        int ex = __shfl_up_sync(~0u, a, 1);
        if (tid == 0) ex = 0;
        int c = ex;
        #pragma unroll
        for (int k = 0; k < 8; k++) {
            int s = tid * 8 + k;
            spanCarry[s] = (unsigned short)c;
            int hr = (spanFR[s] < SPAN);
            c = hr ? (int)spanEnd[s] : c + SPAN;
        }
    }
    __syncthreads();

    // pass B: add incoming carry to pre-first-reset prefix of each span
    {
        const int base = tid * SPAN;
        int c  = spanCarry[tid];
        int fr = spanFR[tid];
        if (c) {
            #pragma unroll
            for (int j = 0; j < SPAN; j++)
                if (j < fr) pos[base + j] = (unsigned short)(pos[base + j] + c);
        }
    }
    __syncthreads();

    // write table + per-segment first reset
    for (int i = tid; i < S_; i += TPREP) {
        int p = pos[i];
        float pf = (float)p;
        g_tbl[b][i] = make_float4((p != 1) ? 1.0f : 0.0f, pf,
                                  __fdividef(1.0f, pf), 0.0f);
        if (p == 1) atomicMin(&s_fr[i / SEGR], i);
    }
    __syncthreads();
    for (int s = tid; s < NSEG; s += TPREP)
        g_fr[b][s] = min(s_fr[s], (s + 1) * SEGR);
}

// ---------------------------------------------------------------------------
// Scan: registers-only streaming, warp = (chain, segment).
// ---------------------------------------------------------------------------
__device__ __forceinline__ float4 ld_cg4(const float4* p) {
    float4 v;
    asm volatile("ld.global.cg.v4.f32 {%0,%1,%2,%3}, [%4];"
                 : "=f"(v.x), "=f"(v.y), "=f"(v.z), "=f"(v.w) : "l"(p));
    return v;
}

__device__ __forceinline__ float4 scan_store(
    const float4* __restrict__ xb, float4* __restrict__ ob,
    const float4* __restrict__ tb, int t, int t1, float4 S)
{
    const size_t rs = D_ / 4;
    for (; t + 8 <= t1; t += 8) {
        float4 xv[8], tv[8];
        #pragma unroll
        for (int j = 0; j < 8; j++) {
            tv[j] = __ldg(tb + t + j);
            xv[j] = __ldg(xb + (size_t)(t + j) * rs);
        }
        #pragma unroll
        for (int j = 0; j < 8; j++) {
            S.x = fmaf(S.x, tv[j].x, xv[j].x * tv[j].y);
            S.y = fmaf(S.y, tv[j].x, xv[j].y * tv[j].y);
            S.z = fmaf(S.z, tv[j].x, xv[j].z * tv[j].y);
            S.w = fmaf(S.w, tv[j].x, xv[j].w * tv[j].y);
            ob[(size_t)(t + j) * rs] =
                make_float4(S.x * tv[j].z, S.y * tv[j].z,
                            S.z * tv[j].z, S.w * tv[j].z);
        }
    }
    for (; t < t1; ++t) {
        float4 tv = __ldg(tb + t);
        float4 xv = __ldg(xb + (size_t)t * rs);
        S.x = fmaf(S.x, tv.x, xv.x * tv.y);
        S.y = fmaf(S.y, tv.x, xv.y * tv.y);
        S.z = fmaf(S.z, tv.x, xv.z * tv.y);
        S.w = fmaf(S.w, tv.x, xv.w * tv.y);
        ob[(size_t)t * rs] = make_float4(S.x * tv.z, S.y * tv.z,
                                         S.z * tv.z, S.w * tv.z);
    }
    return S;
}

__device__ __forceinline__ void publish(int chn, int seg, int l, float4 S) {
    g_sv[chn][seg][l] = S;
    __threadfence();
    __syncwarp();
    if (l == 0) g_sf[chn][seg] = 1;
}

__global__ void __launch_bounds__(WPB * 32)
scan_kernel(const float* __restrict__ emb, float* __restrict__ out)
{
    const int wid = threadIdx.x >> 5;
    const int l   = threadIdx.x & 31;
    const int u   = blockIdx.x * WPB + wid;
    const int seg = u / NCHN;            // segment-major: predecessors earlier
    const int chn = u % NCHN;
    const int b   = chn / NDSL;
    const int dsl = chn % NDSL;
    const int t0  = seg * SEGR, t1 = t0 + SEGR;
    const size_t rs = D_ / 4;

    const float4* xb = (const float4*)emb + (size_t)b * S_ * rs + dsl * 32 + l;
    float4*       ob = (float4*)out       + (size_t)b * S_ * rs + dsl * 32 + l;
    const float4* tb = g_tbl[b];
    const int     fr = g_fr[b][seg];     // first reset row in segment (abs)

    // Phase 1: exact part [fr, t1) — independent of predecessor (m=0 at fr).
    if (fr < t1) {
        float4 S = scan_store(xb, ob, tb, fr, t1, make_float4(0, 0, 0, 0));
        publish(chn, seg, l, S);
    }

    // Phase 2: head rows [t0, fr) — all m=1; seed with predecessor's S.
    if (fr > t0) {
        float4 Sin = make_float4(0, 0, 0, 0);
        if (seg > 0) {
            if (l == 0) {
                while (g_sf[chn][seg - 1] == 0) __nanosleep(64);
            }
            __syncwarp();
            __threadfence();
            Sin = ld_cg4(&g_sv[chn][seg - 1][l]);
        }
        float4 Sh = scan_store(xb, ob, tb, t0, fr, Sin);
        if (fr == t1) publish(chn, seg, l, Sh);   // no-reset segment: final S
    }
}

extern "C" void kernel_launch(void* const* d_in, const int* in_sizes, int n_in,
                              void* d_out, int out_size) {
    const float* emb = (const float*)d_in[0];
    const int*   idw = (const int*)d_in[1];
    float*       out = (float*)d_out;

    (void)in_sizes; (void)n_in; (void)out_size;

    prep_kernel<<<B_, TPREP>>>(idw);
    scan_kernel<<<NBLK, WPB * 32>>>(emb, out);
}

// round 10
// speedup vs baseline: 1.7509x; 1.7509x over previous
#include <cuda_runtime.h>
#include <cstdint>
#include <cstddef>

// Problem shape (fixed by setup_inputs)
#define B_    8
#define S_    4096
#define D_    1024

#define SEGR  128                 // rows per block segment
#define NSEG  (S_ / SEGR)         // 32 segments
#define NBLK  (NSEG * B_)         // 256 blocks (one wave)
#define NTHR  256                 // 8 warps; warp w owns cols [w*128,(w+1)*128)
#define CHK   8                   // rows per register chunk
#define RS    (D_ / 4)            // row stride in float4

// Cross-segment handoff (cleared each launch by clear_kernel)
__device__ volatile int g_run[B_][NSEG];       // runlen+1 leaving seg; 0 = unready
__device__ volatile int g_sf[B_][NSEG];        // S published
__device__ float4       g_sv[B_][NSEG][RS];    // final S per column (1 MB)

__global__ void clear_kernel() {
    int i = threadIdx.x;                        // 256 == B_*NSEG
    ((volatile int*)g_run)[i] = 0;
    ((volatile int*)g_sf)[i]  = 0;
}

__device__ __forceinline__ float4 ld_cg4(const float4* p) {
    float4 v;
    asm volatile("ld.global.cg.v4.f32 {%0,%1,%2,%3}, [%4];"
                 : "=f"(v.x), "=f"(v.y), "=f"(v.z), "=f"(v.w) : "l"(p));
    return v;
}

__global__ void __launch_bounds__(NTHR, 2)
scan_kernel(const float* __restrict__ emb,
            const int*   __restrict__ idw,     // raw 32-bit word view of ids
            float* __restrict__ out)
{
    __shared__ float4   tbl[SEGR];             // (m, n, 1/n, _) per row
    __shared__ unsigned rmask[4];
    __shared__ int      s_fr, s_carry, modeAcc;

    const int tid = threadIdx.x;
    const int w   = tid >> 5;
    const int l   = tid & 31;
    const int bid = blockIdx.x;
    const int b   = bid & (B_ - 1);
    const int seg = bid >> 3;                  // seg-major: preds dispatch earlier
    const int t0  = seg * SEGR;

    // ---- dtype detect on globally-safe window (odd words zero iff int64) ----
    if (tid == 0) { modeAcc = 0; s_carry = 0; }
    __syncthreads();
    {
        int acc = __ldg(&idw[2 * tid + 1]) | __ldg(&idw[2 * (tid + 256) + 1]);
        #pragma unroll
        for (int o = 16; o; o >>= 1) acc |= __shfl_xor_sync(~0u, acc, o);
        if (l == 0) atomicOr(&modeAcc, acc);
    }
    __syncthreads();
    const bool mode64 = (modeAcc == 0);

    // ---- local reset flags + ballot masks (rows = tid for tid<128) ----
    int myf = 0;
    if (tid < SEGR) {
        int gi = b * S_ + t0 + tid;
        if (mode64) {
            int2 v = __ldg(((const int2*)idw) + gi);
            myf = (v.x == 1) & (v.y == 0);
        } else {
            myf = (__ldg(idw + gi) == 1);
        }
        unsigned m = __ballot_sync(~0u, myf);
        if (l == 0) rmask[w] = m;
    }
    __syncthreads();

    // ---- first reset, early runlen publish ----
    if (tid == 0) {
        int fr = SEGR;
        #pragma unroll
        for (int q = 0; q < 4; q++)
            if (rmask[q]) { fr = q * 32 + __ffs(rmask[q]) - 1; break; }
        s_fr = fr;
        if (fr < SEGR) {
            int last = 0;
            #pragma unroll
            for (int q = 3; q >= 0; q--)
                if (rmask[q]) { last = q * 32 + 31 - __clz(rmask[q]); break; }
            g_run[b][seg] = (SEGR - last) + 1;   // runlen + 1
        }
    }
    __syncthreads();
    const int fr = s_fr;

    // ---- exact table for tail rows [fr, SEGR) ----
    if (tid < SEGR && tid >= fr) {
        int q = tid >> 5, li = tid & 31;
        unsigned below = rmask[q] & (0xFFFFFFFFu >> (31 - li));
        int last;
        if (below) last = q * 32 + (31 - __clz(below));
        else {
            last = 0;
            for (int qq = q - 1; qq >= 0; qq--)
                if (rmask[qq]) { last = qq * 32 + 31 - __clz(rmask[qq]); break; }
        }
        float nf = (float)(tid - last + 1);
        tbl[tid] = make_float4(myf ? 0.f : 1.f, nf, __fdividef(1.f, nf), 0.f);
    }
    __syncthreads();

    // ---- register double-buffered streamer over [a, bnd) ----
    const float4* xb = (const float4*)emb + ((size_t)(b * S_ + t0)) * RS + (w << 5) + l;
    float4*       ob = (float4*)out       + ((size_t)(b * S_ + t0)) * RS + (w << 5) + l;

    auto loadChunk = [&](float4* X, int rr, int bnd) {
        #pragma unroll
        for (int j = 0; j < CHK; j++) {
            int row = rr + j; row = row < bnd ? row : bnd - 1;   // clamp (in-bounds)
            X[j] = __ldg(xb + (size_t)row * RS);
        }
    };
    auto compChunk = [&](const float4* X, int rr, int bnd, float4& S) {
        #pragma unroll
        for (int j = 0; j < CHK; j++) {
            int row = rr + j;
            if (row < bnd) {
                float4 t = tbl[row];
                S.x = fmaf(S.x, t.x, X[j].x * t.y);
                S.y = fmaf(S.y, t.x, X[j].y * t.y);
                S.z = fmaf(S.z, t.x, X[j].z * t.y);
                S.w = fmaf(S.w, t.x, X[j].w * t.y);
                ob[(size_t)row * RS] = make_float4(S.x * t.z, S.y * t.z,
                                                   S.z * t.z, S.w * t.z);
            }
        }
    };
    auto stream = [&](int a, int bnd, float4 S) -> float4 {
        if (a >= bnd) return S;
        float4 A[CHK], Bv[CHK];
        int r = a;
        loadChunk(A, r, bnd);
        while (true) {
            if (r + CHK < bnd) loadChunk(Bv, r + CHK, bnd);
            compChunk(A, r, bnd, S);
            r += CHK;
            if (r >= bnd) break;
            if (r + CHK < bnd) loadChunk(A, r + CHK, bnd);
            compChunk(Bv, r, bnd, S);
            r += CHK;
            if (r >= bnd) break;
        }
        return S;
    };

    // ---- phase 1: exact tail [fr, SEGR), seed irrelevant (m=0 at fr) ----
    if (fr < SEGR) {
        float4 S = stream(fr, SEGR, make_float4(0, 0, 0, 0));
        g_sv[b][seg][(w << 5) + l] = S;
        __threadfence();
        __syncthreads();
        if (tid == 0) g_sf[b][seg] = 1;
    }

    // ---- carry wait + head table [0, fr) ----
    if (fr > 0) {
        if (seg > 0) {
            if (tid == 0) {
                int v;
                while ((v = g_run[b][seg - 1]) == 0) __nanosleep(64);
                s_carry = v - 1;
            }
            __syncthreads();
        }
        const int carry = s_carry;
        if (tid < fr) {
            float nf = (float)(tid + 1 + carry);
            tbl[tid] = make_float4(1.f, nf, __fdividef(1.f, nf), 0.f);
        }
        if (fr == SEGR && tid == 0)
            g_run[b][seg] = carry + SEGR + 1;    // whole seg one run
        __syncthreads();

        // ---- S_in wait + phase 2: head [0, fr) seeded with predecessor S ----
        float4 Sin = make_float4(0, 0, 0, 0);
        if (seg > 0) {
            if (tid == 0) {
                while (g_sf[b][seg - 1] == 0) __nanosleep(64);
            }
            __syncthreads();
            __threadfence();
            Sin = ld_cg4(&g_sv[b][seg - 1][(w << 5) + l]);
        }
        float4 Sh = stream(0, fr, Sin);
        if (fr == SEGR) {                        // no reset: final S = head S
            g_sv[b][seg][(w << 5) + l] = Sh;
            __threadfence();
            __syncthreads();
            if (tid == 0) g_sf[b][seg] = 1;
        }
    }
}

extern "C" void kernel_launch(void* const* d_in, const int* in_sizes, int n_in,
                              void* d_out, int out_size) {
    const float* emb = (const float*)d_in[0];
    const int*   idw = (const int*)d_in[1];
    float*       out = (float*)d_out;

    (void)in_sizes; (void)n_in; (void)out_size;

    clear_kernel<<<1, NTHR>>>();                 // reset handoff flags per replay
    scan_kernel<<<NBLK, NTHR>>>(emb, idw, out);
}

// round 12
// speedup vs baseline: 2.1195x; 1.2105x over previous
#include <cuda_runtime.h>
#include <cstdint>
#include <cstddef>

// Problem shape (fixed by setup_inputs)
#define B_    8
#define S_    4096
#define D_    1024

// Tiling
#define NQ    2                  // S-halves per chain
#define SQ    (S_ / NQ)          // 2048 timesteps per block
#define DT    32                 // d-lanes per block
#define NW    8                  // warps per block
#define CW    16                 // timesteps per warp-subchunk
#define CT    (NW * CW)          // 128 timesteps per chunk
#define NC    (SQ / CT)          // 16 chunks per half
#define NTHR  256
#define SPAN  (SQ / NTHR)        // 8 timesteps per thread in pos build
#define NCHAIN 256               // (batch, d-tile) chains
#define NBLK  (NCHAIN * NQ)      // 512 blocks, one wave at 4/SM

// Cross-half handoff. Zero-init at load; producer sets, THE unique consumer
// clears after reading -> invariant holds across graph replays (no clear kernel).
__device__ volatile int g_run[NCHAIN];   // pos[last]+1 leaving half 0; 0 = unready
__device__ volatile int g_sf[NCHAIN];    // final S published
__device__ float        g_sv[NCHAIN][DT];

struct __align__(16) Smem {
    float  xbuf[2][CT][DT];       // 32 KB double-buffered x tile (xbuf[1] holds
                                  //       the 16 KB id window during prologue)
    float4 tbl[2][CT];            // 4 KB per-timestep (m, n, w, c)
    float  aggL[NW][DT];          // 1 KB per-subchunk local sums
    float  aggP[2][NW];           // subchunk carry-kill factors
    unsigned short pos[SQ];       // 4 KB position-in-group (exact after carry)
    unsigned short spanEnd[NTHR];
    unsigned short spanCarry[NTHR];
    unsigned char  spanFR[NTHR];
    int    modeAcc, frqAcc, carryIn;
};                                // ~43.5 KB -> 4 blocks/SM

__device__ __forceinline__ unsigned smem_u32(const void* p) {
    return (unsigned)__cvta_generic_to_shared(p);
}
__device__ __forceinline__ void cp16(unsigned dst, const void* src) {
    asm volatile("cp.async.cg.shared.global [%0], [%1], 16;\n" :: "r"(dst), "l"(src));
}
__device__ __forceinline__ void cp_commit() {
    asm volatile("cp.async.commit_group;\n");
}
__device__ __forceinline__ void cp_wait0() {
    asm volatile("cp.async.wait_group 0;\n" ::: "memory");
}

// Per-chunk table: entries = timesteps; warps 0-3 (tid<128) build. Lane<->entry
// alignment lets one ballot give both the 16-step suffix kill (c) and the
// per-subchunk kill factor P.
__device__ __forceinline__ void build_tbl(Smem* sm, int bb, int cc, int tid) {
    if (tid < CT) {
        const int l = tid & 31;
        int p = sm->pos[cc * CT + tid];
        float pf = (float)p;
        unsigned m32 = __ballot_sync(~0u, p == 1);
        unsigned halfmask = 0xFFFFu << (l & 16);          // 16*(l>>4)
        unsigned above = m32 & ~((2u << l) - 1u) & halfmask;
        float cf = above ? 0.f : pf;
        sm->tbl[bb][tid] = make_float4((p != 1) ? 1.f : 0.f, pf,
                                       __fdividef(1.f, pf), cf);
        if ((l & 15) == 0)
            sm->aggP[bb][tid >> 4] = (m32 & halfmask) ? 0.f : 1.f;
    }
}

__global__ void __launch_bounds__(NTHR, 4)
pool_scan_kernel(const float* __restrict__ emb,
                 const int*   __restrict__ idw,   // raw 32-bit word view of ids
                 float* __restrict__ out)
{
    extern __shared__ char raw[];
    Smem* sm = reinterpret_cast<Smem*>(raw);

    const int bid   = blockIdx.x;
    const int chain = bid & (NCHAIN - 1);
    const int q     = bid >> 8;                 // half index (preds dispatch first)

    const int tid = threadIdx.x;
    const int w   = tid >> 5;
    const int l   = tid & 31;

    const int ndt = D_ / DT;
    const int b   = chain / ndt;
    const int d0  = (chain % ndt) * DT;

    const float* xg  = emb + ((size_t)(b * S_ + q * SQ)) * D_ + d0;
    float*       og0 = out + ((size_t)(b * S_ + q * SQ)) * D_ + d0;

    // ================= prologue =================
    if (tid == 0) { sm->modeAcc = 0; sm->frqAcc = 1 << 30; sm->carryIn = 0; }

    // chunk 0 x-tile -> xbuf[0]  (128 rows x 128 B = 16 KB, 4 cp16/thread)
    #pragma unroll
    for (int k = 0; k < 4; k++) {
        int f = tid + k * NTHR, row = f >> 3, seg = f & 7;
        cp16(smem_u32(&sm->xbuf[0][row][seg * 4]), xg + (size_t)row * D_ + seg * 4);
    }
    cp_commit();
    __syncthreads();

    // dtype detect on globally-safe word window [0,4096): odd words are int64
    // hi-halves (all zero) iff ids are int64 with values in [0,64).
    {
        int acc = 0;
        #pragma unroll
        for (int k = 0; k < 8; k++)
            acc |= __ldg(&idw[2 * (tid * 8 + k) + 1]);
        #pragma unroll
        for (int o = 16; o; o >>= 1) acc |= __shfl_xor_sync(~0u, acc, o);
        if (l == 0) atomicOr(&sm->modeAcc, acc);
    }
    __syncthreads();
    const bool mode64 = (sm->modeAcc == 0);

    // id window for this half -> xbuf[1] scratch (16 KB max, exact fit)
    int* scratch = (int*)&sm->xbuf[1][0][0];
    {
        const size_t ebase = (size_t)b * S_ + q * SQ;
        if (mode64) {
            const int* wsrc = idw + 2 * ebase;       // 4096 words
            #pragma unroll
            for (int k = 0; k < 4; k++) {
                int i4 = tid + k * NTHR;             // 1024 int4
                cp16(smem_u32(scratch + i4 * 4), wsrc + i4 * 4);
            }
        } else {
            const int* wsrc = idw + ebase;           // 2048 words
            #pragma unroll
            for (int k = 0; k < 2; k++) {
                int i4 = tid + k * NTHR;             // 512 int4
                cp16(smem_u32(scratch + i4 * 4), wsrc + i4 * 4);
            }
        }
        cp_commit();
    }
    cp_wait0();
    __syncthreads();

    // --- pos build, pass A (SPAN=8 rows per thread) ---
    {
        const int base = tid * SPAN;
        int p = 0, fr = SPAN;
        #pragma unroll
        for (int j = 0; j < SPAN; j++) {
            int f;
            if (mode64) f = (scratch[2 * (base + j)] == 1) & (scratch[2 * (base + j) + 1] == 0);
            else        f = (scratch[base + j] == 1);
            p = f ? 1 : p + 1;
            if (f && fr == SPAN) fr = j;
            sm->pos[base + j] = (unsigned short)p;
        }
        sm->spanEnd[tid] = (unsigned short)p;
        sm->spanFR[tid]  = (unsigned char)fr;
        if (fr < SPAN) atomicMin(&sm->frqAcc, base + fr);
    }
    __syncthreads();

    // --- span scan (warp 0): carry entering each of 256 spans ---
    if (tid < 32) {
        int a = 0, bb = 1;
        #pragma unroll
        for (int k = 0; k < 8; k++) {
            int s  = tid * 8 + k;
            int hr = (sm->spanFR[s] < SPAN);
            int e  = sm->spanEnd[s];
            if (hr) { a = e; bb = 0; } else { a += SPAN; }
        }
        #pragma unroll
        for (int o = 1; o < 32; o <<= 1) {
            int pa = __shfl_up_sync(~0u, a,  o);
            int pb = __shfl_up_sync(~0u, bb, o);
            if (tid >= o) { a = a + bb * pa; bb = bb * pb; }
        }
        int ex = __shfl_up_sync(~0u, a, 1);
        if (tid == 0) ex = 0;
        int c = ex;
        #pragma unroll
        for (int k = 0; k < 8; k++) {
            int s = tid * 8 + k;
            sm->spanCarry[s] = (unsigned short)c;
            int hr = (sm->spanFR[s] < SPAN);
            c = hr ? (int)sm->spanEnd[s] : c + SPAN;
        }
    }
    __syncthreads();

    // --- pass B: intra-half span carries ---
    {
        const int base = tid * SPAN;
        int c  = sm->spanCarry[tid];
        int fr = sm->spanFR[tid];
        if (c) {
            #pragma unroll
            for (int j = 0; j < SPAN; j++)
                if (j < fr) sm->pos[base + j] = (unsigned short)(sm->pos[base + j] + c);
        }
    }
    __syncthreads();

    const int frq = min(sm->frqAcc, SQ);        // first reset within this half

    // --- cross-half run-length handoff (early; both halves co-resident) ---
    if (q == 0) {
        if (tid == 0) {
            __threadfence();
            g_run[chain] = (int)sm->pos[SQ - 1] + 1;
        }
    } else {
        if (tid == 0) {
            int v;
            while ((v = g_run[chain]) == 0) __nanosleep(64);
            g_run[chain] = 0;                   // consumer-clears for next replay
            sm->carryIn = v - 1;
        }
        __syncthreads();
        const int carry = sm->carryIn;
        for (int t = tid; t < frq; t += NTHR)
            sm->pos[t] = (unsigned short)(sm->pos[t] + carry);
        __syncthreads();
    }

    build_tbl(sm, 0, 0, tid);
    __syncthreads();

    // ================= main loop =================
    float cn = 0.f;                             // half-local affine sum
    const int tb = w * CW;

    for (int c = 0; c < NC; ++c) {
        const int cur = c & 1, nxt = cur ^ 1;
        const bool hasNext = (c + 1 < NC);

        if (hasNext) {
            const int t0n = (c + 1) * CT;
            #pragma unroll
            for (int k = 0; k < 4; k++) {
                int f = tid + k * NTHR, row = f >> 3, seg = f & 7;
                cp16(smem_u32(&sm->xbuf[nxt][row][seg * 4]),
                     xg + (size_t)(t0n + row) * D_ + seg * 4);
            }
            cp_commit();
            build_tbl(sm, nxt, c + 1, tid);     // tbl[nxt] consumed before the
                                                // previous barrier -> safe
        }

        // ---- pass 1: subchunk dot product with folded coefficients ----
        float a0 = 0.f, a1 = 0.f;
        #pragma unroll
        for (int j = 0; j < CW; j += 2) {
            a0 = fmaf(sm->xbuf[cur][tb + j + 0][l], sm->tbl[cur][tb + j + 0].w, a0);
            a1 = fmaf(sm->xbuf[cur][tb + j + 1][l], sm->tbl[cur][tb + j + 1].w, a1);
        }
        sm->aggL[w][l] = a0 + a1;
        __syncthreads();

        // ---- combine ----
        float S = cn, in_S = cn;
        #pragma unroll
        for (int qq = 0; qq < NW; ++qq) {
            if (qq == w) in_S = S;
            S = fmaf(S, sm->aggP[cur][qq], sm->aggL[qq][l]);
        }
        cn = S;

        // ---- pass 2: inclusive scan + write ----
        float Sv = in_S;
        float* ob = og0 + (size_t)(c * CT + tb) * D_ + l;
        #pragma unroll
        for (int j = 0; j < CW; ++j) {
            float4 t4 = sm->tbl[cur][tb + j];
            Sv = fmaf(Sv, t4.x, sm->xbuf[cur][tb + j][l] * t4.y);
            ob[(size_t)j * D_] = Sv * t4.z;
        }

        if (hasNext) cp_wait0();
        __syncthreads();
    }

    // ================= epilogue: S handoff + head fixup =================
    if (q == 0) {
        if (w == 0) g_sv[chain][l] = cn;        // cn identical across warps
        __threadfence();
        __syncthreads();
        if (tid == 0) g_sf[chain] = 1;
    } else if (frq > 0) {
        if (tid == 0) {
            while (g_sf[chain] == 0) __nanosleep(64);
            g_sf[chain] = 0;                    // consumer-clears for next replay
        }
        __syncthreads();
        __threadfence();
        const float S_in = g_sv[chain][l];
        // additive fixup on rows before this half's first reset
        for (int t = w; t < frq; t += NW) {
            float wv = __fdividef(1.0f, (float)sm->pos[t]);
            float* p = og0 + (size_t)t * D_ + l;
            *p = *p + S_in * wv;
        }
    } else {
        if (tid == 0) {                         // frq==0: still consume the flag
            while (g_sf[chain] == 0) __nanosleep(64);
            g_sf[chain] = 0;
        }
    }
}

extern "C" void kernel_launch(void* const* d_in, const int* in_sizes, int n_in,
                              void* d_out, int out_size) {
    const float* emb = (const float*)d_in[0];
    const int*   idw = (const int*)d_in[1];
    float*       out = (float*)d_out;

    (void)in_sizes; (void)n_in; (void)out_size;

    cudaFuncSetAttribute(pool_scan_kernel,
                         cudaFuncAttributeMaxDynamicSharedMemorySize,
                         (int)sizeof(Smem));

    pool_scan_kernel<<<NBLK, NTHR, sizeof(Smem)>>>(emb, idw, out);
}